// round 3
// baseline (speedup 1.0000x reference)
#include <cuda_runtime.h>

// Problem constants
#define BATCH 512
#define SEQ   1024
#define NTAG  50
#define TPAD  52   // pad to multiple of 4 for float4 SMEM reads

// Per-batch partial results (den - num); scratch via __device__ globals (no allocs).
__device__ double g_partial[BATCH];

// Accurate, fast-math-immune expf: Cody-Waite range reduction + degree-7 Horner.
// Valid for |x| < ~80 (inputs here are within +-15). Rel err < ~1.5e-7, ~unbiased.
__device__ __forceinline__ float exp_acc(float x) {
    float n = rintf(x * 1.4426950408889634f);
    float r = fmaf(n, -0.693359375f, x);              // ln2_hi (exact product)
    r = fmaf(n, 2.1219444005469057e-4f, r);           // + n*ln2_lo
    float p = 1.9841270e-4f;                          // 1/5040
    p = fmaf(p, r, 1.3888889e-3f);                    // 1/720
    p = fmaf(p, r, 8.3333333e-3f);                    // 1/120
    p = fmaf(p, r, 4.1666668e-2f);                    // 1/24
    p = fmaf(p, r, 1.6666667e-1f);                    // 1/6
    p = fmaf(p, r, 0.5f);
    p = fmaf(p, r, 1.0f);
    p = fmaf(p, r, 1.0f);
    int ni = (int)n;
    return p * __int_as_float((ni + 127) << 23);
}

// Tag accessor: tags may be int32 (JAX without x64 silently downgrades the
// requested int64) or genuine int64. mode32 selected at runtime.
__device__ __forceinline__ int get_tag(const void* tags, int b, int t, int mode32) {
    if (mode32) return ((const int*)tags)[b * SEQ + t];
    return (int)((const long long*)tags)[b * SEQ + t];
}

// One block per batch, 64 threads (2 warps). Thread j (<50) owns target tag j:
// holds E[:,j] = exp(transitions[:,j]) in registers. Alpha kept in scaled-linear
// domain in double-buffered shared memory; invariant alpha_j = Msum + log(a_j),
// Msum = sumE*ln2 + sumL (exact int exponent sum + double mantissa-log sum).
__global__ void __launch_bounds__(64) crf_main_kernel(
    const float* __restrict__ ts,          // [B,S,T] token_scores
    const void*  __restrict__ tags_raw,    // [B,S] int32 OR int64
    const int*   __restrict__ mask,        // [B,S] int32 (prefix mask)
    const float* __restrict__ trans,       // [T,T]
    const float* __restrict__ startt,      // [T]
    const float* __restrict__ endt)        // [T]
{
    const int b = blockIdx.x;
    const int tid = threadIdx.x;

    __shared__ float ash[2][TPAD];
    __shared__ float red[64];
    __shared__ int   ired[64];

    const float* tsb = ts   + (size_t)b * SEQ * NTAG;
    const int*   mkb = mask + (size_t)b * SEQ;

    // ------------- tags dtype detection (uniform across all threads) --------
    // int64 tags in [0,50) have zero high words; int32 layout puts tags[odd]
    // (nonzero w.p. 1 - 50^-16 over 16 probes) in the high words.
    int any_hi = 0;
    {
        const unsigned long long* p64 = (const unsigned long long*)tags_raw;
        #pragma unroll
        for (int i = 0; i < 16; i++) any_hi |= (int)(p64[i] >> 32);
    }
    const int mode32 = (any_hi != 0);

    // ---------------- sequence length (mask is a prefix mask) ----------------
    int lsum = 0;
    for (int t = tid; t < SEQ; t += 64) lsum += mkb[t];
    ired[tid] = lsum;
    __syncthreads();
    #pragma unroll
    for (int o = 32; o > 0; o >>= 1) {
        if (tid < o) ired[tid] += ired[tid + o];
        __syncthreads();
    }
    const int len = ired[0];   // >= 1 guaranteed

    // ---------------- numerator (gold-path score) ----------------
    float nsum = 0.f;
    for (int t = tid; t < len; t += 64) {
        int tg = get_tag(tags_raw, b, t, mode32);
        nsum += __ldg(tsb + t * NTAG + tg);
        if (t > 0) {
            int tp = get_tag(tags_raw, b, t - 1, mode32);
            nsum += __ldg(trans + tp * NTAG + tg);
        }
    }
    if (tid == 0)
        nsum += __ldg(startt + get_tag(tags_raw, b, 0, mode32))
              + __ldg(endt   + get_tag(tags_raw, b, len - 1, mode32));
    red[tid] = nsum;
    __syncthreads();
    #pragma unroll
    for (int o = 32; o > 0; o >>= 1) {
        if (tid < o) red[tid] += red[tid + o];
        __syncthreads();
    }
    const float num = red[0];
    __syncthreads();

    // ---------------- E column in registers (double-accurate, one-time) -----
    float Ecol[TPAD];
    #pragma unroll
    for (int i = 0; i < TPAD; i++) Ecol[i] = 0.f;
    if (tid < NTAG) {
        #pragma unroll
        for (int i = 0; i < NTAG; i++)
            Ecol[i] = (float)exp((double)__ldg(trans + i * NTAG + tid));
    }

    // ---------------- init alpha (linear domain) ----------------
    if (tid < TPAD) { ash[0][tid] = 0.f; ash[1][tid] = 0.f; }
    __syncthreads();
    if (tid < NTAG)
        ash[0][tid] = (float)exp((double)(__ldg(startt + tid) + tsb[tid]));
    __syncthreads();

    int    sumE = 0;     // exact sum of pivot exponents
    double sumL = 0.0;   // sum of log(mantissa), mantissa in [1,2)
    int cur = 0;

    // Depth-4 emission prefetch pipeline (covers DRAM latency).
    float xb[4];
    #pragma unroll
    for (int k = 0; k < 4; k++) {
        int t = 1 + k; if (t > SEQ - 1) t = SEQ - 1;
        xb[k] = (tid < NTAG) ? __ldg(tsb + (size_t)t * NTAG + tid) : 0.f;
    }

    for (int tb = 1; tb < len; tb += 4) {
        float xn[4];
        #pragma unroll
        for (int k = 0; k < 4; k++) {
            int t = tb + 4 + k; if (t > SEQ - 1) t = SEQ - 1;
            xn[k] = (tid < NTAG) ? __ldg(tsb + (size_t)t * NTAG + tid) : 0.f;
        }
        #pragma unroll
        for (int k = 0; k < 4; k++) {
            int t = tb + k;
            if (t < len) {   // uniform across block
                const float4* a4 = (const float4*)(ash[cur]);
                float4 v = a4[0];
                float s = v.x;                    // normalization pivot a[0] > 0
                float acc0 = v.x * Ecol[0];
                float acc1 = v.y * Ecol[1];
                float acc2 = v.z * Ecol[2];
                float acc3 = v.w * Ecol[3];
                #pragma unroll
                for (int q = 1; q < 13; q++) {
                    v = a4[q];
                    acc0 = fmaf(v.x, Ecol[4 * q + 0], acc0);
                    acc1 = fmaf(v.y, Ecol[4 * q + 1], acc1);
                    acc2 = fmaf(v.z, Ecol[4 * q + 2], acc2);
                    acc3 = fmaf(v.w, Ecol[4 * q + 3], acc3);
                }
                float dot = (acc0 + acc1) + (acc2 + acc3);
                float anew = dot * __frcp_rn(s) * exp_acc(xb[k]);
                // log(s) split: s = m * 2^e, m in [1,2). Exponent sum exact.
                int sbits = __float_as_int(s);
                sumE += ((sbits >> 23) & 255) - 127;
                float m = __int_as_float((sbits & 0x007FFFFF) | 0x3F800000);
                sumL += (double)__logf(m);
                if (tid < NTAG) ash[cur ^ 1][tid] = anew;
                cur ^= 1;
                __syncthreads();
            }
        }
        xb[0] = xn[0]; xb[1] = xn[1]; xb[2] = xn[2]; xb[3] = xn[3];
    }

    // ---------------- denominator ----------------
    float w = (tid < NTAG)
            ? ash[cur][tid] * (float)exp((double)__ldg(endt + tid)) : 0.f;
    red[tid] = w;
    __syncthreads();
    #pragma unroll
    for (int o = 32; o > 0; o >>= 1) {
        if (tid < o) red[tid] += red[tid + o];
        __syncthreads();
    }
    if (tid == 0) {
        double den = (double)sumE * 0.6931471805599453
                   + sumL + log((double)red[0]);
        g_partial[b] = den - (double)num;
    }
}

// Deterministic final reduction of the 512 per-batch partials (double).
__global__ void crf_finalize_kernel(float* __restrict__ out)
{
    __shared__ double sh[BATCH];
    int t = threadIdx.x;
    sh[t] = g_partial[t];
    __syncthreads();
    #pragma unroll
    for (int o = 256; o > 0; o >>= 1) {
        if (t < o) sh[t] += sh[t + o];
        __syncthreads();
    }
    if (t == 0) out[0] = (float)(sh[0] * (1.0 / (double)BATCH));
}

extern "C" void kernel_launch(void* const* d_in, const int* in_sizes, int n_in,
                              void* d_out, int out_size)
{
    const float* token_scores = (const float*)d_in[0];
    const void*  tags         = (const void*)d_in[1];
    const int*   token_mask   = (const int*)d_in[2];
    const float* transitions  = (const float*)d_in[3];
    const float* start_trans  = (const float*)d_in[4];
    const float* end_trans    = (const float*)d_in[5];
    float* out = (float*)d_out;

    crf_main_kernel<<<BATCH, 64>>>(token_scores, tags, token_mask,
                                   transitions, start_trans, end_trans);
    crf_finalize_kernel<<<1, BATCH>>>(out);
}

// round 4
// speedup vs baseline: 1.3079x; 1.3079x over previous
#include <cuda_runtime.h>

// Problem constants
#define BATCH 512
#define SEQ   1024
#define NTAG  50
#define TPAD  52          // padded tag count (multiple of 4)
#define WPB   4           // warps (=batches) per block
#define NBLK  (BATCH / WPB)

// Per-batch partial results (den - num); scratch via __device__ global (no allocs).
__device__ double g_partial[BATCH];

// ----------------------------- f32x2 helpers --------------------------------
typedef unsigned long long u64;

__device__ __forceinline__ u64 pk2(float lo, float hi) {
    u64 r; asm("mov.b64 %0,{%1,%2};" : "=l"(r) : "f"(lo), "f"(hi)); return r;
}
__device__ __forceinline__ void upk2(float& lo, float& hi, u64 v) {
    asm("mov.b64 {%0,%1},%2;" : "=f"(lo), "=f"(hi) : "l"(v));
}
__device__ __forceinline__ u64 fma2_(u64 a, u64 b, u64 c) {
    u64 d; asm("fma.rn.f32x2 %0,%1,%2,%3;" : "=l"(d) : "l"(a), "l"(b), "l"(c)); return d;
}
__device__ __forceinline__ u64 mul2_(u64 a, u64 b) {
    u64 d; asm("mul.rn.f32x2 %0,%1,%2;" : "=l"(d) : "l"(a), "l"(b)); return d;
}
__device__ __forceinline__ u64 add2_(u64 a, u64 b) {
    u64 d; asm("add.rn.f32x2 %0,%1,%2;" : "=l"(d) : "l"(a), "l"(b)); return d;
}

// Accurate expf (one-time init paths): Cody-Waite + degree-7 Horner.
__device__ __forceinline__ float exp_acc(float x) {
    float n = rintf(x * 1.4426950408889634f);
    float r = fmaf(n, -0.693359375f, x);
    r = fmaf(n, 2.1219444005469057e-4f, r);
    float p = 1.9841270e-4f;
    p = fmaf(p, r, 1.3888889e-3f);
    p = fmaf(p, r, 8.3333333e-3f);
    p = fmaf(p, r, 4.1666668e-2f);
    p = fmaf(p, r, 1.6666667e-1f);
    p = fmaf(p, r, 0.5f);
    p = fmaf(p, r, 1.0f);
    p = fmaf(p, r, 1.0f);
    return p * __int_as_float(((int)n + 127) << 23);
}

// Cheap packed exp for per-step emissions (MUFU.EX2 path, ample accuracy margin).
__device__ __forceinline__ u64 pexpf2(u64 x2) {
    float x0, x1; upk2(x0, x1, x2);
    return pk2(__expf(x0), __expf(x1));
}

// Tags may be int32 (JAX w/o x64 silently downgrades int64) or genuine int64.
__device__ __forceinline__ int get_tag(const void* tags, int b, int t, int mode32) {
    if (mode32) return ((const int*)tags)[b * SEQ + t];
    return (int)((const long long*)tags)[b * SEQ + t];
}

__device__ __forceinline__ float warp_red_f(float v) {
    #pragma unroll
    for (int o = 16; o > 0; o >>= 1) v += __shfl_xor_sync(0xffffffffu, v, o);
    return v;
}
__device__ __forceinline__ int warp_red_i(int v) {
    #pragma unroll
    for (int o = 16; o > 0; o >>= 1) v += __shfl_xor_sync(0xffffffffu, v, o);
    return v;
}

// One WARP per batch (4 warps/block, grid=128 -> <=1 block/SM, 1 warp/SMSP).
// Lane j (<25) owns output tags 2j, 2j+1 (f32x2 packed). Alpha kept in
// scaled-linear domain, DUPLICATED in shared ((a_i,a_i) u64) so the dot is
// pure LDS.128 -> fma.f32x2. Pivot is an exact power of two extracted from
// a_0's exponent bits: scaling is exact, log(pivot)=e*ln2 exact int sum.
__global__ void __launch_bounds__(32 * WPB, 1) crf_main_kernel(
    const float* __restrict__ ts,          // [B,S,T] token_scores
    const void*  __restrict__ tags_raw,    // [B,S] int32 OR int64
    const int*   __restrict__ mask,        // [B,S] int32 (prefix mask)
    const float* __restrict__ trans,       // [T,T]
    const float* __restrict__ startt,      // [T]
    const float* __restrict__ endt)        // [T]
{
    const int warp = threadIdx.x >> 5;
    const int lane = threadIdx.x & 31;
    const int b    = blockIdx.x * WPB + warp;
    const int owner = (lane < 25);
    const int j0 = 2 * lane, j1 = 2 * lane + 1;   // owned tags (if owner)

    // Per-warp double-buffered duplicated alpha: u64 dup[i] = (a_i, a_i).
    __shared__ __align__(16) u64 dup[WPB][2][TPAD];

    const float* tsb = ts   + (size_t)b * SEQ * NTAG;
    const int*   mkb = mask + (size_t)b * SEQ;

    // ---------------- tags dtype detection (uniform) ----------------
    int any_hi = 0;
    {
        const u64* p64 = (const u64*)tags_raw;
        #pragma unroll
        for (int i = 0; i < 16; i++) any_hi |= (int)(p64[i] >> 32);
    }
    const int mode32 = (any_hi != 0);

    // ---------------- sequence length (prefix mask) ----------------
    int ls = 0;
    for (int t = lane; t < SEQ; t += 32) ls += mkb[t];
    const int len = warp_red_i(ls);    // >= 1

    // ---------------- numerator (gold-path score) ----------------
    float nsum = 0.f;
    for (int t = lane; t < len; t += 32) {
        int tg = get_tag(tags_raw, b, t, mode32);
        nsum += __ldg(tsb + t * NTAG + tg);
        if (t > 0) {
            int tp = get_tag(tags_raw, b, t - 1, mode32);
            nsum += __ldg(trans + tp * NTAG + tg);
        }
    }
    if (lane == 0)
        nsum += __ldg(startt + get_tag(tags_raw, b, 0, mode32))
              + __ldg(endt   + get_tag(tags_raw, b, len - 1, mode32));
    const float num = warp_red_f(nsum);

    // ---------------- E pairs in registers: Ecol2[i] = (E[i][j0], E[i][j1]) --
    u64 Ecol2[TPAD];
    #pragma unroll
    for (int i = 0; i < TPAD; i++) {
        float elo = 0.f, ehi = 0.f;
        if (i < NTAG && owner) {
            elo = exp_acc(__ldg(trans + i * NTAG + j0));
            ehi = exp_acc(__ldg(trans + i * NTAG + j1));
        }
        Ecol2[i] = pk2(elo, ehi);
    }

    // ---------------- init alpha ----------------
    u64* d0 = dup[warp][0];
    u64* d1 = dup[warp][1];
    if (owner) {
        float alo = exp_acc(__ldg(startt + j0) + tsb[j0]);
        float ahi = exp_acc(__ldg(startt + j1) + tsb[j1]);
        d0[j0] = pk2(alo, alo);
        d0[j1] = pk2(ahi, ahi);
    }
    if (lane == 25) {           // zero pads in BOTH buffers (never rewritten)
        d0[50] = 0; d0[51] = 0; d1[50] = 0; d1[51] = 0;
    }
    __syncwarp();

    int  sumE = 0;   // exact pivot-exponent sum
    int  cur  = 0;

    // Depth-4 raw-emission prefetch (packed pair per lane), exp 1 step ahead.
    u64 xb[4];
    #pragma unroll
    for (int k = 0; k < 4; k++) {
        int t = 1 + k; if (t > SEQ - 1) t = SEQ - 1;
        xb[k] = owner ? pk2(__ldg(tsb + (size_t)t * NTAG + j0),
                            __ldg(tsb + (size_t)t * NTAG + j1)) : 0ull;
    }
    u64 ecur = pexpf2(xb[0]);

    for (int tb = 1; tb < len; tb += 4) {
        u64 xn[4];
        #pragma unroll
        for (int k = 0; k < 4; k++) {
            int t = tb + 4 + k; if (t > SEQ - 1) t = SEQ - 1;
            xn[k] = owner ? pk2(__ldg(tsb + (size_t)t * NTAG + j0),
                                __ldg(tsb + (size_t)t * NTAG + j1)) : 0ull;
        }
        #pragma unroll
        for (int k = 0; k < 4; k++) {
            int t = tb + k;
            if (t < len) {    // warp-uniform
                // exp for NEXT step (independent of alpha -> overlaps dot)
                u64 enext = pexpf2((k < 3) ? xb[k + 1] : xn[0]);

                const ulonglong2* av = (const ulonglong2*)dup[warp][cur];
                u64* dn = dup[warp][cur ^ 1];

                // pivot exponent from a_0 (exact power-of-2 scaling)
                float a0, a0d; upk2(a0, a0d, ((const u64*)av)[0]);

                u64 aA = 0, aB = 0, aC = 0, aD = 0;
                #pragma unroll
                for (int q = 0; q < 13; q++) {
                    ulonglong2 v0 = av[2 * q];      // i = 4q, 4q+1
                    ulonglong2 v1 = av[2 * q + 1];  // i = 4q+2, 4q+3
                    aA = fma2_(v0.x, Ecol2[4 * q + 0], aA);
                    aB = fma2_(v0.y, Ecol2[4 * q + 1], aB);
                    aC = fma2_(v1.x, Ecol2[4 * q + 2], aC);
                    aD = fma2_(v1.y, Ecol2[4 * q + 3], aD);
                }
                u64 dot2 = add2_(add2_(aA, aB), add2_(aC, aD));

                int eb = (__float_as_int(a0) >> 23) & 255;
                sumE += eb - 127;
                float fac = __int_as_float((254 - eb) << 23);  // 2^{-e}, exact

                u64 anew2 = mul2_(mul2_(dot2, pk2(fac, fac)), ecur);
                ecur = enext;

                if (owner) {
                    float alo, ahi; upk2(alo, ahi, anew2);
                    dn[j0] = pk2(alo, alo);
                    dn[j1] = pk2(ahi, ahi);
                }
                cur ^= 1;
                __syncwarp();
            }
        }
        xb[0] = xn[0]; xb[1] = xn[1]; xb[2] = xn[2]; xb[3] = xn[3];
    }

    // ---------------- denominator ----------------
    float part = 0.f;
    if (owner) {
        float alo, ahi, t0, t1;
        upk2(alo, t0, dup[warp][cur][j0]);
        upk2(ahi, t1, dup[warp][cur][j1]);
        part = alo * exp_acc(__ldg(endt + j0)) + ahi * exp_acc(__ldg(endt + j1));
    }
    part = warp_red_f(part);
    if (lane == 0) {
        double den = (double)sumE * 0.6931471805599453 + log((double)part);
        g_partial[b] = den - (double)num;
    }
}

// Deterministic final reduction of the 512 per-batch partials (double).
__global__ void crf_finalize_kernel(float* __restrict__ out)
{
    __shared__ double sh[BATCH];
    int t = threadIdx.x;
    sh[t] = g_partial[t];
    __syncthreads();
    #pragma unroll
    for (int o = 256; o > 0; o >>= 1) {
        if (t < o) sh[t] += sh[t + o];
        __syncthreads();
    }
    if (t == 0) out[0] = (float)(sh[0] * (1.0 / (double)BATCH));
}

extern "C" void kernel_launch(void* const* d_in, const int* in_sizes, int n_in,
                              void* d_out, int out_size)
{
    const float* token_scores = (const float*)d_in[0];
    const void*  tags         = (const void*)d_in[1];
    const int*   token_mask   = (const int*)d_in[2];
    const float* transitions  = (const float*)d_in[3];
    const float* start_trans  = (const float*)d_in[4];
    const float* end_trans    = (const float*)d_in[5];
    float* out = (float*)d_out;

    crf_main_kernel<<<NBLK, 32 * WPB>>>(token_scores, tags, token_mask,
                                        transitions, start_trans, end_trans);
    crf_finalize_kernel<<<1, BATCH>>>(out);
}

// round 5
// speedup vs baseline: 2.3586x; 1.8033x over previous
#include <cuda_runtime.h>

// Problem constants
#define BATCH 512
#define SEQ   1024
#define NTAG  50
#define TPAD  52          // padded tag count (multiple of 4)
#define WPB   4           // warps (=batches) per block
#define NBLK  (BATCH / WPB)

// Per-batch partial results (den - num); scratch via __device__ global (no allocs).
__device__ double g_partial[BATCH];

// ----------------------------- f32x2 helpers --------------------------------
typedef unsigned long long u64;

__device__ __forceinline__ u64 pk2(float lo, float hi) {
    u64 r; asm("mov.b64 %0,{%1,%2};" : "=l"(r) : "f"(lo), "f"(hi)); return r;
}
__device__ __forceinline__ void upk2(float& lo, float& hi, u64 v) {
    asm("mov.b64 {%0,%1},%2;" : "=f"(lo), "=f"(hi) : "l"(v));
}
__device__ __forceinline__ u64 fma2_(u64 a, u64 b, u64 c) {
    u64 d; asm("fma.rn.f32x2 %0,%1,%2,%3;" : "=l"(d) : "l"(a), "l"(b), "l"(c)); return d;
}
__device__ __forceinline__ u64 mul2_(u64 a, u64 b) {
    u64 d; asm("mul.rn.f32x2 %0,%1,%2;" : "=l"(d) : "l"(a), "l"(b)); return d;
}
__device__ __forceinline__ u64 add2_(u64 a, u64 b) {
    u64 d; asm("add.rn.f32x2 %0,%1,%2;" : "=l"(d) : "l"(a), "l"(b)); return d;
}

// Accurate expf (one-time init paths): Cody-Waite + degree-7 Horner.
__device__ __forceinline__ float exp_acc(float x) {
    float n = rintf(x * 1.4426950408889634f);
    float r = fmaf(n, -0.693359375f, x);
    r = fmaf(n, 2.1219444005469057e-4f, r);
    float p = 1.9841270e-4f;
    p = fmaf(p, r, 1.3888889e-3f);
    p = fmaf(p, r, 8.3333333e-3f);
    p = fmaf(p, r, 4.1666668e-2f);
    p = fmaf(p, r, 1.6666667e-1f);
    p = fmaf(p, r, 0.5f);
    p = fmaf(p, r, 1.0f);
    p = fmaf(p, r, 1.0f);
    return p * __int_as_float(((int)n + 127) << 23);
}

// Cheap packed exp for per-step emissions (MUFU.EX2 path, ample accuracy margin).
__device__ __forceinline__ u64 pexpf2(u64 x2) {
    float x0, x1; upk2(x0, x1, x2);
    return pk2(__expf(x0), __expf(x1));
}

// Tags may be int32 (JAX w/o x64 silently downgrades int64) or genuine int64.
__device__ __forceinline__ int get_tag(const void* tags, int b, int t, int mode32) {
    if (mode32) return ((const int*)tags)[b * SEQ + t];
    return (int)((const long long*)tags)[b * SEQ + t];
}

__device__ __forceinline__ float warp_red_f(float v) {
    #pragma unroll
    for (int o = 16; o > 0; o >>= 1) v += __shfl_xor_sync(0xffffffffu, v, o);
    return v;
}
__device__ __forceinline__ int warp_red_i(int v) {
    #pragma unroll
    for (int o = 16; o > 0; o >>= 1) v += __shfl_xor_sync(0xffffffffu, v, o);
    return v;
}

// One WARP per batch (4 warps/block, grid=128 -> <=1 block/SM, 1 warp/SMSP).
// Lane L (<25) owns outputs j0=2L, j1=2L+1. Alpha stored PLAIN (50 floats) in
// double-buffered shared; each fma2 multiplies an adjacent SOURCE PAIR
// (a_2q, a_2q+1) -- read directly as packed u64 from SMEM (13 LDS.128/step) --
// by the matching E pair for one output. Renormalization by an exact power of
// two (from a_0's exponent) every 4 steps; exponent sum kept exactly in int.
__global__ void __launch_bounds__(32 * WPB, 1) crf_main_kernel(
    const float* __restrict__ ts,          // [B,S,T] token_scores
    const void*  __restrict__ tags_raw,    // [B,S] int32 OR int64
    const int*   __restrict__ mask,        // [B,S] int32 (prefix mask)
    const float* __restrict__ trans,       // [T,T]
    const float* __restrict__ startt,      // [T]
    const float* __restrict__ endt)        // [T]
{
    const int warp = threadIdx.x >> 5;
    const int lane = threadIdx.x & 31;
    const int b    = blockIdx.x * WPB + warp;
    const int owner = (lane < 25);
    const int j0 = 2 * lane, j1 = 2 * lane + 1;

    // Per-warp double-buffered plain alpha (52 floats = 13 x 16B).
    __shared__ __align__(16) float ash[WPB][2][TPAD];

    const float* tsb = ts   + (size_t)b * SEQ * NTAG;
    const int*   mkb = mask + (size_t)b * SEQ;

    // ---------------- tags dtype detection (uniform) ----------------
    int any_hi = 0;
    {
        const u64* p64 = (const u64*)tags_raw;
        #pragma unroll
        for (int i = 0; i < 16; i++) any_hi |= (int)(p64[i] >> 32);
    }
    const int mode32 = (any_hi != 0);

    // ---------------- sequence length (prefix mask) ----------------
    int ls = 0;
    for (int t = lane; t < SEQ; t += 32) ls += mkb[t];
    const int len = warp_red_i(ls);    // >= 1

    // ---------------- numerator (gold-path score) ----------------
    float nsum = 0.f;
    for (int t = lane; t < len; t += 32) {
        int tg = get_tag(tags_raw, b, t, mode32);
        nsum += __ldg(tsb + t * NTAG + tg);
        if (t > 0) {
            int tp = get_tag(tags_raw, b, t - 1, mode32);
            nsum += __ldg(trans + tp * NTAG + tg);
        }
    }
    if (lane == 0)
        nsum += __ldg(startt + get_tag(tags_raw, b, 0, mode32))
              + __ldg(endt   + get_tag(tags_raw, b, len - 1, mode32));
    const float num = warp_red_f(nsum);

    // ------- E source-pairs per owned output: E0[q]=(E[2q][j0],E[2q+1][j0]) --
    u64 E0[26], E1[26];
    #pragma unroll
    for (int q = 0; q < 26; q++) {
        float e00 = 0.f, e01 = 0.f, e10 = 0.f, e11 = 0.f;
        if (owner) {
            int i0 = 2 * q, i1 = 2 * q + 1;
            if (i0 < NTAG) {
                e00 = exp_acc(__ldg(trans + i0 * NTAG + j0));
                e10 = exp_acc(__ldg(trans + i0 * NTAG + j1));
            }
            if (i1 < NTAG) {
                e01 = exp_acc(__ldg(trans + i1 * NTAG + j0));
                e11 = exp_acc(__ldg(trans + i1 * NTAG + j1));
            }
        }
        E0[q] = pk2(e00, e01);
        E1[q] = pk2(e10, e11);
    }

    // ---------------- init alpha ----------------
    float* a0f = ash[warp][0];
    float* a1f = ash[warp][1];
    if (owner) {
        a0f[j0] = exp_acc(__ldg(startt + j0) + tsb[j0]);
        a0f[j1] = exp_acc(__ldg(startt + j1) + tsb[j1]);
    }
    if (lane == 25) {   // zero pads in BOTH buffers (never rewritten)
        a0f[50] = 0.f; a0f[51] = 0.f; a1f[50] = 0.f; a1f[51] = 0.f;
    }
    __syncwarp();

    int sumE = 0;
    int cur  = 0;

    // Emission prefetch: packed u64 (j0,j1 adjacent -> single LDG.64).
    u64 xb[4];
    #pragma unroll
    for (int k = 0; k < 4; k++) {
        int t = 1 + k; if (t > SEQ - 1) t = SEQ - 1;
        xb[k] = owner ? __ldg((const u64*)(tsb + (size_t)t * NTAG + j0)) : 0ull;
    }

    // One forward step. renorm: apply 2^-e scaling (e from a_0) this step.
    auto step = [&](u64 ex, bool renorm) {
        const float* af = ash[warp][cur];
        const ulonglong2* av = (const ulonglong2*)af;
        float* an = ash[warp][cur ^ 1];

        float fac = 1.0f;
        if (renorm) {
            int eb = (__float_as_int(af[0]) >> 23) & 255;
            sumE += eb - 127;
            fac = __int_as_float((254 - eb) << 23);   // 2^{-e}, exact
        }

        u64 A0 = 0, B0 = 0, A1 = 0, B1 = 0;
        #pragma unroll
        for (int q = 0; q < 13; q++) {
            ulonglong2 v = av[q];     // v.x=(a_4q,a_4q+1)  v.y=(a_4q+2,a_4q+3)
            A0 = fma2_(v.x, E0[2 * q],     A0);
            B0 = fma2_(v.y, E0[2 * q + 1], B0);
            A1 = fma2_(v.x, E1[2 * q],     A1);
            B1 = fma2_(v.y, E1[2 * q + 1], B1);
        }
        u64 s0 = add2_(A0, B0), s1 = add2_(A1, B1);
        float p0, q0, p1, q1;
        upk2(p0, q0, s0); upk2(p1, q1, s1);
        u64 anew = mul2_(pk2(p0 + q0, p1 + q1), ex);
        if (renorm) anew = mul2_(anew, pk2(fac, fac));
        if (owner) *(u64*)(an + j0) = anew;          // STS.64
        cur ^= 1;
        __syncwarp();
    };

    int tb = 1;
    for (; tb + 3 < len; tb += 4) {               // full 4-step blocks
        u64 xn[4];
        #pragma unroll
        for (int k = 0; k < 4; k++) {
            int t = tb + 4 + k; if (t > SEQ - 1) t = SEQ - 1;
            xn[k] = owner ? __ldg((const u64*)(tsb + (size_t)t * NTAG + j0)) : 0ull;
        }
        u64 e0 = pexpf2(xb[0]), e1 = pexpf2(xb[1]),
            e2 = pexpf2(xb[2]), e3 = pexpf2(xb[3]);
        step(e0, true);            // tb = 1 mod 4: renormalize
        step(e1, false);
        step(e2, false);
        step(e3, false);
        xb[0] = xn[0]; xb[1] = xn[1]; xb[2] = xn[2]; xb[3] = xn[3];
    }
    for (int t = tb; t < len; t++)                 // tail (<=3 steps)
        step(pexpf2(xb[t - tb]), (t & 3) == 1);

    // ---------------- denominator ----------------
    float part = 0.f;
    if (owner) {
        const float* af = ash[warp][cur];
        part = af[j0] * exp_acc(__ldg(endt + j0))
             + af[j1] * exp_acc(__ldg(endt + j1));
    }
    part = warp_red_f(part);
    if (lane == 0) {
        double den = (double)sumE * 0.6931471805599453 + log((double)part);
        g_partial[b] = den - (double)num;
    }
}

// Deterministic final reduction of the 512 per-batch partials (double).
__global__ void crf_finalize_kernel(float* __restrict__ out)
{
    __shared__ double sh[BATCH];
    int t = threadIdx.x;
    sh[t] = g_partial[t];
    __syncthreads();
    #pragma unroll
    for (int o = 256; o > 0; o >>= 1) {
        if (t < o) sh[t] += sh[t + o];
        __syncthreads();
    }
    if (t == 0) out[0] = (float)(sh[0] * (1.0 / (double)BATCH));
}

// No-op: pads the launch sequence to 5 per call so ncu (-s 5 -c 1) lands on
// the MAIN kernel (index 5 mod 5 == 0 -> crf_main_kernel of the 2nd call).
__global__ void crf_dummy_kernel() {}

extern "C" void kernel_launch(void* const* d_in, const int* in_sizes, int n_in,
                              void* d_out, int out_size)
{
    const float* token_scores = (const float*)d_in[0];
    const void*  tags         = (const void*)d_in[1];
    const int*   token_mask   = (const int*)d_in[2];
    const float* transitions  = (const float*)d_in[3];
    const float* start_trans  = (const float*)d_in[4];
    const float* end_trans    = (const float*)d_in[5];
    float* out = (float*)d_out;

    crf_main_kernel<<<NBLK, 32 * WPB>>>(token_scores, tags, token_mask,
                                        transitions, start_trans, end_trans);
    crf_finalize_kernel<<<1, BATCH>>>(out);
    crf_dummy_kernel<<<1, 1>>>();
    crf_dummy_kernel<<<1, 1>>>();
    crf_dummy_kernel<<<1, 1>>>();
}

// round 6
// speedup vs baseline: 2.4429x; 1.0357x over previous
#include <cuda_runtime.h>

// Problem constants
#define BATCH 512
#define SEQ   1024
#define NTAG  50
#define TPAD  52          // padded tag count (multiple of 4)
#define WPB   4           // warps (=batches) per block
#define NBLK  (BATCH / WPB)

// Scratch via __device__ globals (no allocs). Counter self-resets each run.
__device__ double g_partial[BATCH];
__device__ unsigned int g_done = 0;

// ----------------------------- f32x2 helpers --------------------------------
typedef unsigned long long u64;

__device__ __forceinline__ u64 pk2(float lo, float hi) {
    u64 r; asm("mov.b64 %0,{%1,%2};" : "=l"(r) : "f"(lo), "f"(hi)); return r;
}
__device__ __forceinline__ void upk2(float& lo, float& hi, u64 v) {
    asm("mov.b64 {%0,%1},%2;" : "=f"(lo), "=f"(hi) : "l"(v));
}
__device__ __forceinline__ u64 fma2_(u64 a, u64 b, u64 c) {
    u64 d; asm("fma.rn.f32x2 %0,%1,%2,%3;" : "=l"(d) : "l"(a), "l"(b), "l"(c)); return d;
}
__device__ __forceinline__ u64 mul2_(u64 a, u64 b) {
    u64 d; asm("mul.rn.f32x2 %0,%1,%2;" : "=l"(d) : "l"(a), "l"(b)); return d;
}
__device__ __forceinline__ u64 add2_(u64 a, u64 b) {
    u64 d; asm("add.rn.f32x2 %0,%1,%2;" : "=l"(d) : "l"(a), "l"(b)); return d;
}

// Accurate expf (one-time init paths): Cody-Waite + degree-7 Horner.
__device__ __forceinline__ float exp_acc(float x) {
    float n = rintf(x * 1.4426950408889634f);
    float r = fmaf(n, -0.693359375f, x);
    r = fmaf(n, 2.1219444005469057e-4f, r);
    float p = 1.9841270e-4f;
    p = fmaf(p, r, 1.3888889e-3f);
    p = fmaf(p, r, 8.3333333e-3f);
    p = fmaf(p, r, 4.1666668e-2f);
    p = fmaf(p, r, 1.6666667e-1f);
    p = fmaf(p, r, 0.5f);
    p = fmaf(p, r, 1.0f);
    p = fmaf(p, r, 1.0f);
    return p * __int_as_float(((int)n + 127) << 23);
}

// Cheap packed exp for per-step emissions (MUFU.EX2 path, ample accuracy margin).
__device__ __forceinline__ u64 pexpf2(u64 x2) {
    float x0, x1; upk2(x0, x1, x2);
    return pk2(__expf(x0), __expf(x1));
}

// Tags may be int32 (JAX w/o x64 silently downgrades int64) or genuine int64.
__device__ __forceinline__ int get_tag(const void* tags, int b, int t, int mode32) {
    if (mode32) return ((const int*)tags)[b * SEQ + t];
    return (int)((const long long*)tags)[b * SEQ + t];
}

__device__ __forceinline__ float warp_red_f(float v) {
    #pragma unroll
    for (int o = 16; o > 0; o >>= 1) v += __shfl_xor_sync(0xffffffffu, v, o);
    return v;
}
__device__ __forceinline__ int warp_red_i(int v) {
    #pragma unroll
    for (int o = 16; o > 0; o >>= 1) v += __shfl_xor_sync(0xffffffffu, v, o);
    return v;
}

// One WARP per batch (4 warps/block, grid=128 -> 1 block/SM, 1 warp/SMSP).
// Lane L (<25) owns outputs j0=2L, j1=2L+1. Alpha stored PLAIN (50+2 floats)
// in double-buffered shared; each fma2 multiplies an adjacent SOURCE PAIR
// (a_2q, a_2q+1) -- read packed from SMEM (13 LDS.128/step, broadcast) -- by
// the matching E pair for one output. Renorm by an exact power of two (from
// a_0's exponent) every 4 steps, folded into the emission factor OFF the
// critical path; exponent sum kept exactly in int. Final loss reduced in the
// last-finishing block (atomic counter), single kernel launch total.
__global__ void __launch_bounds__(32 * WPB, 1) crf_main_kernel(
    const float* __restrict__ ts,          // [B,S,T] token_scores
    const void*  __restrict__ tags_raw,    // [B,S] int32 OR int64
    const int*   __restrict__ mask,        // [B,S] int32 (prefix mask)
    const float* __restrict__ trans,       // [T,T]
    const float* __restrict__ startt,      // [T]
    const float* __restrict__ endt,        // [T]
    float* __restrict__ out)               // [1]
{
    const int warp = threadIdx.x >> 5;
    const int lane = threadIdx.x & 31;
    const int b    = blockIdx.x * WPB + warp;
    const int owner = (lane < 25);
    const int j0 = 2 * lane, j1 = 2 * lane + 1;

    // Per-warp double-buffered plain alpha (52 floats = 13 x 16B).
    __shared__ __align__(16) float ash[WPB][2][TPAD];
    __shared__ double red_sh[32 * WPB];

    const float* tsb = ts   + (size_t)b * SEQ * NTAG;
    const int*   mkb = mask + (size_t)b * SEQ;

    // ---------------- tags dtype detection (uniform) ----------------
    int any_hi = 0;
    {
        const u64* p64 = (const u64*)tags_raw;
        #pragma unroll
        for (int i = 0; i < 16; i++) any_hi |= (int)(p64[i] >> 32);
    }
    const int mode32 = (any_hi != 0);

    // ---------------- sequence length (prefix mask) ----------------
    int ls = 0;
    for (int t = lane; t < SEQ; t += 32) ls += mkb[t];
    const int len = warp_red_i(ls);    // >= 1

    // ---------------- numerator (gold-path score) ----------------
    float nsum = 0.f;
    for (int t = lane; t < len; t += 32) {
        int tg = get_tag(tags_raw, b, t, mode32);
        nsum += __ldg(tsb + t * NTAG + tg);
        if (t > 0) {
            int tp = get_tag(tags_raw, b, t - 1, mode32);
            nsum += __ldg(trans + tp * NTAG + tg);
        }
    }
    if (lane == 0)
        nsum += __ldg(startt + get_tag(tags_raw, b, 0, mode32))
              + __ldg(endt   + get_tag(tags_raw, b, len - 1, mode32));
    const float num = warp_red_f(nsum);

    // ------- E source-pairs per owned output: E0[q]=(E[2q][j0],E[2q+1][j0]) --
    u64 E0[26], E1[26];
    #pragma unroll
    for (int q = 0; q < 26; q++) {
        float e00 = 0.f, e01 = 0.f, e10 = 0.f, e11 = 0.f;
        if (owner) {
            int i0 = 2 * q, i1 = 2 * q + 1;
            if (i0 < NTAG) {
                e00 = exp_acc(__ldg(trans + i0 * NTAG + j0));
                e10 = exp_acc(__ldg(trans + i0 * NTAG + j1));
            }
            if (i1 < NTAG) {
                e01 = exp_acc(__ldg(trans + i1 * NTAG + j0));
                e11 = exp_acc(__ldg(trans + i1 * NTAG + j1));
            }
        }
        E0[q] = pk2(e00, e01);
        E1[q] = pk2(e10, e11);
    }

    // ---------------- init alpha ----------------
    float* a0f = ash[warp][0];
    float* a1f = ash[warp][1];
    if (owner) {
        a0f[j0] = exp_acc(__ldg(startt + j0) + tsb[j0]);
        a0f[j1] = exp_acc(__ldg(startt + j1) + tsb[j1]);
    }
    if (lane == 25) {   // zero pads in BOTH buffers (never rewritten)
        a0f[50] = 0.f; a0f[51] = 0.f; a1f[50] = 0.f; a1f[51] = 0.f;
    }
    __syncwarp();

    int sumE = 0;
    int cur  = 0;

    // Emission prefetch: packed u64 (j0,j1 adjacent -> single LDG.64).
    u64 xb[4];
    #pragma unroll
    for (int k = 0; k < 4; k++) {
        int t = 1 + k; if (t > SEQ - 1) t = SEQ - 1;
        xb[k] = owner ? __ldg((const u64*)(tsb + (size_t)t * NTAG + j0)) : 0ull;
    }

    // One forward step. renorm: fold exact 2^-e scaling (e from a_0) into ex
    // OFF the dot's critical path.
    auto step = [&](u64 ex, bool renorm) {
        const float* af = ash[warp][cur];
        const ulonglong2* av = (const ulonglong2*)af;
        float* an = ash[warp][cur ^ 1];

        if (renorm) {
            // Early scalar LDS of pivot; fac-mul overlaps the dot below.
            int eb = (__float_as_int(af[0]) >> 23) & 255;
            sumE += eb - 127;
            float fac = __int_as_float((254 - eb) << 23);   // 2^{-e}, exact
            ex = mul2_(ex, pk2(fac, fac));
        }

        u64 A0 = 0, B0 = 0, A1 = 0, B1 = 0;
        #pragma unroll
        for (int q = 0; q < 13; q++) {
            ulonglong2 v = av[q];     // v.x=(a_4q,a_4q+1)  v.y=(a_4q+2,a_4q+3)
            A0 = fma2_(v.x, E0[2 * q],     A0);
            B0 = fma2_(v.y, E0[2 * q + 1], B0);
            A1 = fma2_(v.x, E1[2 * q],     A1);
            B1 = fma2_(v.y, E1[2 * q + 1], B1);
        }
        u64 s0 = add2_(A0, B0), s1 = add2_(A1, B1);
        float p0, q0, p1, q1;
        upk2(p0, q0, s0); upk2(p1, q1, s1);
        u64 anew = mul2_(pk2(p0 + q0, p1 + q1), ex);
        if (owner) *(u64*)(an + j0) = anew;          // STS.64
        cur ^= 1;
        __syncwarp();
    };

    int tb = 1;
    for (; tb + 3 < len; tb += 4) {               // full 4-step blocks
        u64 xn[4];
        #pragma unroll
        for (int k = 0; k < 4; k++) {
            int t = tb + 4 + k; if (t > SEQ - 1) t = SEQ - 1;
            xn[k] = owner ? __ldg((const u64*)(tsb + (size_t)t * NTAG + j0)) : 0ull;
        }
        u64 e0 = pexpf2(xb[0]), e1 = pexpf2(xb[1]),
            e2 = pexpf2(xb[2]), e3 = pexpf2(xb[3]);
        step(e0, true);            // tb = 1 mod 4: renormalize
        step(e1, false);
        step(e2, false);
        step(e3, false);
        xb[0] = xn[0]; xb[1] = xn[1]; xb[2] = xn[2]; xb[3] = xn[3];
    }
    for (int t = tb; t < len; t++)                 // tail (<=3 steps)
        step(pexpf2(xb[t - tb]), (t & 3) == 1);

    // ---------------- denominator + per-batch partial ----------------
    float part = 0.f;
    if (owner) {
        const float* af = ash[warp][cur];
        part = af[j0] * exp_acc(__ldg(endt + j0))
             + af[j1] * exp_acc(__ldg(endt + j1));
    }
    part = warp_red_f(part);
    if (lane == 0) {
        double den = (double)sumE * 0.6931471805599453 + log((double)part);
        g_partial[b] = den - (double)num;
    }

    // ---------------- last-block final reduction (deterministic) ----------
    __syncthreads();
    __threadfence();
    __shared__ unsigned int is_last;
    if (threadIdx.x == 0)
        is_last = (atomicAdd(&g_done, 1u) == (unsigned)(NBLK - 1));
    __syncthreads();
    if (is_last) {
        const int tid = threadIdx.x;           // 128 threads
        double s = 0.0;
        #pragma unroll
        for (int i = 0; i < BATCH / (32 * WPB); i++)   // 4 strided reads, fixed order
            s += g_partial[tid + i * (32 * WPB)];
        red_sh[tid] = s;
        __syncthreads();
        #pragma unroll
        for (int o = 64; o > 0; o >>= 1) {
            if (tid < o) red_sh[tid] += red_sh[tid + o];
            __syncthreads();
        }
        if (tid == 0) {
            out[0] = (float)(red_sh[0] * (1.0 / (double)BATCH));
            g_done = 0;                        // reset for next graph replay
        }
    }
}

extern "C" void kernel_launch(void* const* d_in, const int* in_sizes, int n_in,
                              void* d_out, int out_size)
{
    const float* token_scores = (const float*)d_in[0];
    const void*  tags         = (const void*)d_in[1];
    const int*   token_mask   = (const int*)d_in[2];
    const float* transitions  = (const float*)d_in[3];
    const float* start_trans  = (const float*)d_in[4];
    const float* end_trans    = (const float*)d_in[5];
    float* out = (float*)d_out;

    crf_main_kernel<<<NBLK, 32 * WPB>>>(token_scores, tags, token_mask,
                                        transitions, start_trans, end_trans, out);
}

// round 7
// speedup vs baseline: 2.9055x; 1.1894x over previous
#include <cuda_runtime.h>

// Problem constants
#define BATCH 512
#define SEQ   1024
#define NTAG  50
#define TPAD  52          // padded tag count (multiple of 4)
#define BPB   4           // batches per block
#define NBLK  (BATCH / BPB)
#define NTHR  256         // 8 warps: w<4 fwd, w>=4 bwd; wid%4 = SMSP pairing

// Scratch via __device__ globals (no allocs). Counter self-resets each run.
__device__ double g_partial[BATCH];
__device__ unsigned int g_done = 0;

// ----------------------------- f32x2 helpers --------------------------------
typedef unsigned long long u64;

__device__ __forceinline__ u64 pk2(float lo, float hi) {
    u64 r; asm("mov.b64 %0,{%1,%2};" : "=l"(r) : "f"(lo), "f"(hi)); return r;
}
__device__ __forceinline__ void upk2(float& lo, float& hi, u64 v) {
    asm("mov.b64 {%0,%1},%2;" : "=f"(lo), "=f"(hi) : "l"(v));
}
__device__ __forceinline__ u64 fma2_(u64 a, u64 b, u64 c) {
    u64 d; asm("fma.rn.f32x2 %0,%1,%2,%3;" : "=l"(d) : "l"(a), "l"(b), "l"(c)); return d;
}
__device__ __forceinline__ u64 mul2_(u64 a, u64 b) {
    u64 d; asm("mul.rn.f32x2 %0,%1,%2;" : "=l"(d) : "l"(a), "l"(b)); return d;
}
__device__ __forceinline__ u64 add2_(u64 a, u64 b) {
    u64 d; asm("add.rn.f32x2 %0,%1,%2;" : "=l"(d) : "l"(a), "l"(b)); return d;
}

// Accurate expf (one-time init paths): Cody-Waite + degree-7 Horner.
__device__ __forceinline__ float exp_acc(float x) {
    float n = rintf(x * 1.4426950408889634f);
    float r = fmaf(n, -0.693359375f, x);
    r = fmaf(n, 2.1219444005469057e-4f, r);
    float p = 1.9841270e-4f;
    p = fmaf(p, r, 1.3888889e-3f);
    p = fmaf(p, r, 8.3333333e-3f);
    p = fmaf(p, r, 4.1666668e-2f);
    p = fmaf(p, r, 1.6666667e-1f);
    p = fmaf(p, r, 0.5f);
    p = fmaf(p, r, 1.0f);
    p = fmaf(p, r, 1.0f);
    return p * __int_as_float(((int)n + 127) << 23);
}

// Cheap packed exp for per-step emissions (MUFU.EX2 path, ample accuracy margin).
__device__ __forceinline__ u64 pexpf2(u64 x2) {
    float x0, x1; upk2(x0, x1, x2);
    return pk2(__expf(x0), __expf(x1));
}

// Tags may be int32 (JAX w/o x64 silently downgrades int64) or genuine int64.
__device__ __forceinline__ int get_tag(const void* tags, int b, int t, int mode32) {
    if (mode32) return ((const int*)tags)[b * SEQ + t];
    return (int)((const long long*)tags)[b * SEQ + t];
}

__device__ __forceinline__ float warp_red_f(float v) {
    #pragma unroll
    for (int o = 16; o > 0; o >>= 1) v += __shfl_xor_sync(0xffffffffu, v, o);
    return v;
}
__device__ __forceinline__ int warp_red_i(int v) {
    #pragma unroll
    for (int o = 16; o > 0; o >>= 1) v += __shfl_xor_sync(0xffffffffu, v, o);
    return v;
}
__device__ __forceinline__ double warp_red_d(double v) {
    #pragma unroll
    for (int o = 16; o > 0; o >>= 1) v += __shfl_xor_sync(0xffffffffu, v, o);
    return v;
}

// Forward/backward split: den = log sum_i alpha_M[i] * beta_M[i].
//   fwd warp: alpha_t = (alpha_{t-1} E) .* ex_t,  t = 1..M          (M steps)
//   bwd warp: beta_t  = E (ex_{t+1} .* beta_{t+1}), t = len-2..M    (len-1-M)
// with beta_{len-1} = exp(end). Both in scaled-linear domain, exact pow2
// renorm every 4 steps (int exponent sums). Per block: 4 batches x 2 warps;
// warp w and w+4 (same batch) share an SMSP (wid%4) -> mutual latency hiding.
__global__ void __launch_bounds__(NTHR, 1) crf_main_kernel(
    const float* __restrict__ ts,          // [B,S,T] token_scores
    const void*  __restrict__ tags_raw,    // [B,S] int32 OR int64
    const int*   __restrict__ mask,        // [B,S] int32 (prefix mask)
    const float* __restrict__ trans,       // [T,T]
    const float* __restrict__ startt,      // [T]
    const float* __restrict__ endt,        // [T]
    float* __restrict__ out)               // [1]
{
    const int w    = threadIdx.x >> 5;
    const int lane = threadIdx.x & 31;
    const int bq   = w & 3;                 // batch slot in block
    const int dir  = w >> 2;                // 0 = fwd, 1 = bwd
    const int b    = blockIdx.x * BPB + bq;
    const int owner = (lane < 25);
    const int j0 = 2 * lane, j1 = 2 * lane + 1;

    __shared__ __align__(16) float afb[BPB][2][TPAD];   // fwd alpha buffers
    __shared__ __align__(16) float cbb[BPB][2][TPAD];   // bwd c buffers
    __shared__ float  betaf[BPB][TPAD];                 // final raw beta_M
    __shared__ float  num_sh[BPB];
    __shared__ int    sEb_sh[BPB];
    __shared__ double red_sh[NTHR];
    __shared__ unsigned int is_last;

    const float* tsb = ts   + (size_t)b * SEQ * NTAG;
    const int*   mkb = mask + (size_t)b * SEQ;

    // ---------------- sequence length (prefix mask) ----------------
    int ls = 0;
    for (int t = lane; t < SEQ; t += 32) ls += mkb[t];
    const int len = warp_red_i(ls);    // >= 1
    const int M   = len >> 1;          // meet point
    const int nb  = len - 1 - M;       // backward step count

    int sumEf = 0, curf = 0;           // fwd state (live only in fwd warps)

    if (dir == 0) {
        // =================== FORWARD WARP ===================
        // E source-pairs per owned output col: E0[q]=(E[2q][j0],E[2q+1][j0]).
        u64 E0[26], E1[26];
        #pragma unroll
        for (int q = 0; q < 26; q++) {
            float e00 = 0.f, e01 = 0.f, e10 = 0.f, e11 = 0.f;
            if (owner) {
                int i0 = 2 * q, i1 = 2 * q + 1;
                if (i0 < NTAG) {
                    e00 = exp_acc(__ldg(trans + i0 * NTAG + j0));
                    e10 = exp_acc(__ldg(trans + i0 * NTAG + j1));
                }
                if (i1 < NTAG) {
                    e01 = exp_acc(__ldg(trans + i1 * NTAG + j0));
                    e11 = exp_acc(__ldg(trans + i1 * NTAG + j1));
                }
            }
            E0[q] = pk2(e00, e01);
            E1[q] = pk2(e10, e11);
        }

        float* a0f = afb[bq][0];
        float* a1f = afb[bq][1];
        if (owner) {
            a0f[j0] = exp_acc(__ldg(startt + j0) + tsb[j0]);
            a0f[j1] = exp_acc(__ldg(startt + j1) + tsb[j1]);
        }
        if (lane == 25) {   // zero pads in BOTH buffers (avoid NaN via 0*garbage)
            a0f[50] = 0.f; a0f[51] = 0.f; a1f[50] = 0.f; a1f[51] = 0.f;
        }
        __syncwarp();

        const int lenf = M + 1;        // steps t = 1..M

        u64 xb[4];
        #pragma unroll
        for (int k = 0; k < 4; k++) {
            int t = 1 + k; if (t > SEQ - 1) t = SEQ - 1;
            xb[k] = owner ? __ldg((const u64*)(tsb + (size_t)t * NTAG + j0)) : 0ull;
        }

        auto fstep = [&](u64 ex, bool renorm) {
            const float* af = afb[bq][curf];
            const ulonglong2* av = (const ulonglong2*)af;
            float* an = afb[bq][curf ^ 1];
            if (renorm) {
                int eb = (__float_as_int(af[0]) >> 23) & 255;
                sumEf += eb - 127;
                float fac = __int_as_float((254 - eb) << 23);   // 2^{-e}, exact
                ex = mul2_(ex, pk2(fac, fac));
            }
            u64 A0 = 0, B0 = 0, A1 = 0, B1 = 0;
            #pragma unroll
            for (int q = 0; q < 13; q++) {
                ulonglong2 v = av[q];
                A0 = fma2_(v.x, E0[2 * q],     A0);
                B0 = fma2_(v.y, E0[2 * q + 1], B0);
                A1 = fma2_(v.x, E1[2 * q],     A1);
                B1 = fma2_(v.y, E1[2 * q + 1], B1);
            }
            u64 s0 = add2_(A0, B0), s1 = add2_(A1, B1);
            float p0, q0, p1, q1;
            upk2(p0, q0, s0); upk2(p1, q1, s1);
            u64 anew = mul2_(pk2(p0 + q0, p1 + q1), ex);
            if (owner) *(u64*)(an + j0) = anew;
            curf ^= 1;
            __syncwarp();
        };

        int tb = 1;
        for (; tb + 3 < lenf; tb += 4) {
            u64 xn[4];
            #pragma unroll
            for (int k = 0; k < 4; k++) {
                int t = tb + 4 + k; if (t > SEQ - 1) t = SEQ - 1;
                xn[k] = owner ? __ldg((const u64*)(tsb + (size_t)t * NTAG + j0)) : 0ull;
            }
            u64 e0 = pexpf2(xb[0]), e1 = pexpf2(xb[1]),
                e2 = pexpf2(xb[2]), e3 = pexpf2(xb[3]);
            fstep(e0, true);
            fstep(e1, false);
            fstep(e2, false);
            fstep(e3, false);
            xb[0] = xn[0]; xb[1] = xn[1]; xb[2] = xn[2]; xb[3] = xn[3];
        }
        for (int t = tb; t < lenf; t++)
            fstep(pexpf2(xb[t - tb]), (t & 3) == 1);
    } else {
        // =================== BACKWARD WARP ===================
        // Tags dtype detection (uniform): int64 tags in [0,50) -> zero hi words.
        int any_hi = 0;
        {
            const u64* p64 = (const u64*)tags_raw;
            #pragma unroll
            for (int i = 0; i < 16; i++) any_hi |= (int)(p64[i] >> 32);
        }
        const int mode32 = (any_hi != 0);

        // Numerator (gold-path score).
        float nsum = 0.f;
        for (int t = lane; t < len; t += 32) {
            int tg = get_tag(tags_raw, b, t, mode32);
            nsum += __ldg(tsb + t * NTAG + tg);
            if (t > 0) {
                int tp = get_tag(tags_raw, b, t - 1, mode32);
                nsum += __ldg(trans + tp * NTAG + tg);
            }
        }
        if (lane == 0)
            nsum += __ldg(startt + get_tag(tags_raw, b, 0, mode32))
                  + __ldg(endt   + get_tag(tags_raw, b, len - 1, mode32));
        nsum = warp_red_f(nsum);
        if (lane == 0) num_sh[bq] = nsum;

        int sumEb = 0;

        if (nb == 0) {
            // No backward steps: beta_M = exp(end) raw.
            if (owner) {
                betaf[bq][j0] = exp_acc(__ldg(endt + j0));
                betaf[bq][j1] = exp_acc(__ldg(endt + j1));
            }
        } else {
            // E row-pairs per owned output row: ER0[q]=(E[i0][2q],E[i0][2q+1]).
            u64 ER0[26], ER1[26];
            #pragma unroll
            for (int q = 0; q < 26; q++) {
                float e00 = 0.f, e01 = 0.f, e10 = 0.f, e11 = 0.f;
                if (owner) {
                    int c0 = 2 * q, c1 = 2 * q + 1;
                    if (c0 < NTAG) {
                        e00 = exp_acc(__ldg(trans + j0 * NTAG + c0));
                        e10 = exp_acc(__ldg(trans + j1 * NTAG + c0));
                    }
                    if (c1 < NTAG) {
                        e01 = exp_acc(__ldg(trans + j0 * NTAG + c1));
                        e11 = exp_acc(__ldg(trans + j1 * NTAG + c1));
                    }
                }
                ER0[q] = pk2(e00, e01);
                ER1[q] = pk2(e10, e11);
            }

            float* c0f = cbb[bq][0];
            float* c1f = cbb[bq][1];
            if (owner) {   // c_j = exp(x_{len-1}[j] + end_j)
                c0f[j0] = exp_acc(tsb[(size_t)(len - 1) * NTAG + j0] + __ldg(endt + j0));
                c0f[j1] = exp_acc(tsb[(size_t)(len - 1) * NTAG + j1] + __ldg(endt + j1));
            }
            if (lane == 25) {
                c0f[50] = 0.f; c0f[51] = 0.f; c1f[50] = 0.f; c1f[51] = 0.f;
            }
            __syncwarp();

            int curb = 0;
            const int nbm1 = nb - 1;   // normal steps; last step stores raw

            // Emission prefetch, DECREASING t: iteration idx uses x_{len-2-idx}.
            u64 xb[4];
            #pragma unroll
            for (int k = 0; k < 4; k++) {
                int t = len - 2 - k; if (t < 0) t = 0;
                xb[k] = owner ? __ldg((const u64*)(tsb + (size_t)t * NTAG + j0)) : 0ull;
            }

            auto bstep = [&](u64 ex, bool renorm, bool fin) {
                const float* cf = cbb[bq][curb];
                const ulonglong2* cv = (const ulonglong2*)cf;
                float* cn = cbb[bq][curb ^ 1];
                if (renorm) {
                    int eb = (__float_as_int(cf[0]) >> 23) & 255;
                    sumEb += eb - 127;
                    float fac = __int_as_float((254 - eb) << 23);
                    ex = mul2_(ex, pk2(fac, fac));
                }
                u64 A0 = 0, B0 = 0, A1 = 0, B1 = 0;
                #pragma unroll
                for (int q = 0; q < 13; q++) {
                    ulonglong2 v = cv[q];
                    A0 = fma2_(v.x, ER0[2 * q],     A0);
                    B0 = fma2_(v.y, ER0[2 * q + 1], B0);
                    A1 = fma2_(v.x, ER1[2 * q],     A1);
                    B1 = fma2_(v.y, ER1[2 * q + 1], B1);
                }
                u64 s0 = add2_(A0, B0), s1 = add2_(A1, B1);
                float p0, q0, p1, q1;
                upk2(p0, q0, s0); upk2(p1, q1, s1);
                if (fin) {
                    if (owner) {
                        betaf[bq][j0] = p0 + q0;
                        betaf[bq][j1] = p1 + q1;
                    }
                } else {
                    u64 cnew = mul2_(pk2(p0 + q0, p1 + q1), ex);
                    if (owner) *(u64*)(cn + j0) = cnew;
                }
                curb ^= 1;
                __syncwarp();
            };

            int idx = 0;
            for (; idx + 3 < nbm1; idx += 4) {
                u64 xn[4];
                #pragma unroll
                for (int k = 0; k < 4; k++) {
                    int t = len - 2 - (idx + 4 + k); if (t < 0) t = 0;
                    xn[k] = owner ? __ldg((const u64*)(tsb + (size_t)t * NTAG + j0)) : 0ull;
                }
                u64 e0 = pexpf2(xb[0]), e1 = pexpf2(xb[1]),
                    e2 = pexpf2(xb[2]), e3 = pexpf2(xb[3]);
                bstep(e0, true, false);
                bstep(e1, false, false);
                bstep(e2, false, false);
                bstep(e3, false, false);
                xb[0] = xn[0]; xb[1] = xn[1]; xb[2] = xn[2]; xb[3] = xn[3];
            }
            for (int k = 0; idx < nbm1; idx++, k++)
                bstep(pexpf2(xb[k]), (idx & 3) == 0, false);

            bstep(0ull, false, true);      // final: store raw beta_M
        }

        if (lane == 0) sEb_sh[bq] = sumEb;
    }

    // ---------------- combine: den = ln2*(sEf+sEb) + log(sum alpha*beta) ----
    __syncthreads();
    if (dir == 0) {
        double part = 0.0;
        if (owner) {
            const float* af = afb[bq][curf];
            part = (double)af[j0] * (double)betaf[bq][j0]
                 + (double)af[j1] * (double)betaf[bq][j1];
        }
        part = warp_red_d(part);
        if (lane == 0) {
            double den = (double)(sumEf + sEb_sh[bq]) * 0.6931471805599453
                       + log(part);
            g_partial[b] = den - (double)num_sh[bq];
        }
    }

    // ---------------- last-block final reduction (deterministic) ----------
    __syncthreads();
    __threadfence();
    if (threadIdx.x == 0)
        is_last = (atomicAdd(&g_done, 1u) == (unsigned)(NBLK - 1));
    __syncthreads();
    if (is_last) {
        const int tid = threadIdx.x;           // 256 threads, 512 partials
        double s = g_partial[tid] + g_partial[tid + NTHR];
        red_sh[tid] = s;
        __syncthreads();
        #pragma unroll
        for (int o = 128; o > 0; o >>= 1) {
            if (tid < o) red_sh[tid] += red_sh[tid + o];
            __syncthreads();
        }
        if (tid == 0) {
            out[0] = (float)(red_sh[0] * (1.0 / (double)BATCH));
            g_done = 0;                        // reset for next graph replay
        }
    }
}

extern "C" void kernel_launch(void* const* d_in, const int* in_sizes, int n_in,
                              void* d_out, int out_size)
{
    const float* token_scores = (const float*)d_in[0];
    const void*  tags         = (const void*)d_in[1];
    const int*   token_mask   = (const int*)d_in[2];
    const float* transitions  = (const float*)d_in[3];
    const float* start_trans  = (const float*)d_in[4];
    const float* end_trans    = (const float*)d_in[5];
    float* out = (float*)d_out;

    crf_main_kernel<<<NBLK, NTHR>>>(token_scores, tags, token_mask,
                                    transitions, start_trans, end_trans, out);
}